// round 17
// baseline (speedup 1.0000x reference)
#include <cuda_runtime.h>

// img: [256, 3, 224, 224] f32, y_idx/x_idx: [256] i32.
// out[b,c,h,w] = img * (0 if h in [y,y+32) && x-range else 1)
//
// Concurrent dual-engine split (R9 decomposition showed CE ~7.2 TB/s vs SM
// path 6.03 TB/s -> plateau is SM-request-path, not HBM):
//   CE  : memcpy batches [0,140)  on capture stream          (~22.3 us alone)
//   SM  : champion streamer, batches [140,256), forked stream (~22.1 us alone)
//   then: 2-us fixup zeroes squares in the CE range.
// Stream-capture fork/join via events; stream+events created per call
// (host-side objects, no device allocation).

#define SQ 32
#define BATCH 256
#define CH 3
#define HH 224
#define WW 224
#define W4 (WW / 4)                    // 56 float4 per row
#define TY 4
#define RPT 8
#define TILE_H (TY * RPT)              // 32 rows per block

#define CE_B 140                       // batches handled by copy engine
#define SM_B (BATCH - CE_B)            // 116 batches on SM streamer
#define PLANE_F4 (HH * W4)             // 12544
#define BATCH_F4 (CH * PLANE_F4)       // 37632
#define CE_BYTES ((size_t)CE_B * BATCH_F4 * 16)

// ---------------- SM streamer (champion config) over a batch range --------
__global__ __launch_bounds__(W4 * TY)
void sm_stream_kernel(const float4* __restrict__ img,
                      const int* __restrict__ y_idx,
                      const int* __restrict__ x_idx,
                      float4* __restrict__ out) {
    const int b  = blockIdx.z;                       // local batch (offset ptrs)
    const int c  = blockIdx.y;
    const int h0 = blockIdx.x * TILE_H + threadIdx.y;
    const int w4 = threadIdx.x;

    const int y = __ldg(&y_idx[b]);
    const int x = __ldg(&x_idx[b]);

    const long plane = ((long)b * CH + c) * (long)PLANE_F4;
    const long base  = plane + (long)h0 * W4 + w4;

    float4 v[RPT];
#pragma unroll
    for (int k = 0; k < RPT; k++)
        v[k] = __ldcs(&img[base + (long)(k * TY) * W4]);

    const int w0 = w4 * 4;
    const bool cx0 = (unsigned)(w0     - x) < SQ;
    const bool cx1 = (unsigned)(w0 + 1 - x) < SQ;
    const bool cx2 = (unsigned)(w0 + 2 - x) < SQ;
    const bool cx3 = (unsigned)(w0 + 3 - x) < SQ;

    if (cx0 || cx1 || cx2 || cx3) {
#pragma unroll
        for (int k = 0; k < RPT; k++) {
            const int h = h0 + k * TY;
            if ((unsigned)(h - y) < SQ) {
                if (cx0) v[k].x = 0.f;
                if (cx1) v[k].y = 0.f;
                if (cx2) v[k].z = 0.f;
                if (cx3) v[k].w = 0.f;
            }
        }
    }

#pragma unroll
    for (int k = 0; k < RPT; k++)
        __stcs(&out[base + (long)(k * TY) * W4], v[k]);
}

// ---------------- fixup: zero squares in CE range [0, CE_B) ---------------
// Segments: CE_B*3*32 row-segments of 32 floats (128 B, coalesced per warp).
// Each warp handles 4 segments. 13440 segs -> 3360 warps -> 420 CTAs.
#define FIX_SEGS (CE_B * CH * SQ)
#define FIX_WARPS (FIX_SEGS / 4)
#define FIX_CTAS (FIX_WARPS / 8)

__global__ __launch_bounds__(256)
void fixup_kernel(float* __restrict__ out,
                  const int* __restrict__ y_idx,
                  const int* __restrict__ x_idx) {
    const int warp = blockIdx.x * 8 + (threadIdx.x >> 5);
    const int lane = threadIdx.x & 31;

#pragma unroll
    for (int s = 0; s < 4; s++) {
        const int seg = warp * 4 + s;
        const int r   = seg & (SQ - 1);
        const int bc  = seg >> 5;
        const int c   = bc % CH;
        const int b   = bc / CH;
        const int y   = __ldg(&y_idx[b]);
        const int x   = __ldg(&x_idx[b]);
        const long off = (((long)b * CH + c) * HH + (y + r)) * WW + x + lane;
        out[off] = 0.0f;
    }
}

extern "C" void kernel_launch(void* const* d_in, const int* in_sizes, int n_in,
                              void* d_out, int out_size) {
    const float* img  = (const float*)d_in[0];
    const int* y_idx  = (const int*)d_in[1];
    const int* x_idx  = (const int*)d_in[2];
    float* out        = (float*)d_out;

    // Fork a second captured stream (host-side objects only; leaked —
    // kernel_launch is called a bounded number of times by the harness).
    cudaStream_t s1;
    cudaStreamCreateWithFlags(&s1, cudaStreamNonBlocking);
    cudaEvent_t eFork, eJoin;
    cudaEventCreateWithFlags(&eFork, cudaEventDisableTiming);
    cudaEventCreateWithFlags(&eJoin, cudaEventDisableTiming);

    // Fork: s1 branches off the capture origin stream.
    cudaEventRecord(eFork, 0);
    cudaStreamWaitEvent(s1, eFork, 0);

    // SM engine: batches [CE_B, 256) on s1 (concurrent with the CE copy).
    {
        const long off_f4 = (long)CE_B * BATCH_F4;
        dim3 block(W4, TY);                   // 224 threads
        dim3 grid(HH / TILE_H, CH, SM_B);     // 7 x 3 x 116
        sm_stream_kernel<<<grid, block, 0, s1>>>(
            (const float4*)img + off_f4, y_idx + CE_B, x_idx + CE_B,
            (float4*)out + off_f4);
    }

    // Copy engine: batches [0, CE_B) on the origin stream.
    cudaMemcpyAsync(out, img, CE_BYTES, cudaMemcpyDeviceToDevice, 0);

    // Fixup the CE range (ordered after the memcpy on the origin stream).
    fixup_kernel<<<FIX_CTAS, 256>>>(out, y_idx, x_idx);

    // Join s1 back into the origin stream.
    cudaEventRecord(eJoin, s1);
    cudaStreamWaitEvent(0, eJoin, 0);
}